// round 4
// baseline (speedup 1.0000x reference)
#include <cuda_runtime.h>
#include <math.h>

#define MAX_N 1024
#define EPS 1e-4f
#define CHUNKS 4

// ---- scratch (__device__ globals; no allocation allowed) ----
__device__ int   g_lookup[MAX_N * MAX_N];   // 4 MB: (i,j) -> directed edge id, -1 if none
__device__ float g_diag  [MAX_N * 64];      // per-node sum of R^T R
__device__ float g_dis   [MAX_N * 64];      // per-node D^{-1/2}

// ---- fill reverse-lookup table ----
__global__ void k_lookup(const int* __restrict__ E, int P, int n) {
    int p = blockIdx.x * blockDim.x + threadIdx.x;
    if (p >= P) return;
    int i = E[2 * p];
    int j = E[2 * p + 1];
    g_lookup[i * n + j] = p;
}

// ---- per-edge FtF = R^T R, atomically accumulated into g_diag[i] ----
__global__ void k_ftf(const float* __restrict__ R, const int* __restrict__ E,
                      int P, int n) {
    int gid = blockIdx.x * blockDim.x + threadIdx.x;
    if (gid >= P * 64) return;
    int p = gid >> 6;
    int e = gid & 63;
    int r = e >> 3, c = e & 7;
    int i = E[2 * p];
    const float* Rp = R + (size_t)p * 64;
    float v = 0.f;
#pragma unroll
    for (int k = 0; k < 8; k++) v += Rp[k * 8 + r] * Rp[k * 8 + c];
    atomicAdd(&g_diag[i * 64 + e], v);
}

// ---- per-node D^{-1/2} via coupled Newton-Schulz (SPD, lambda >= EPS) ----
__global__ void k_ns(int n) {
    __shared__ float Y[64], Z[64], G[64], red[64];
    int v = blockIdx.x;
    int t = threadIdx.x;
    int r = t >> 3, c = t & 7;

    float a = g_diag[v * 64 + r * 8 + c];
    float b = g_diag[v * 64 + c * 8 + r];
    float d = 0.5f * (a + b) + ((r == c) ? EPS : 0.f);

    red[t] = d * d;
    __syncthreads();
    if (t < 32) red[t] += red[t + 32];
    __syncthreads();
    if (t < 32) {
        float s = red[t];
#pragma unroll
        for (int o = 16; o > 0; o >>= 1) s += __shfl_down_sync(0xffffffffu, s, o);
        if (t == 0) red[0] = s;
    }
    __syncthreads();
    float s = sqrtf(red[0]);
    float inv_s = 1.f / s;

    Y[t] = d * inv_s;
    Z[t] = (r == c) ? 1.f : 0.f;
    __syncthreads();

    for (int it = 0; it < 24; it++) {
        float acc = 0.f;
#pragma unroll
        for (int k = 0; k < 8; k++) acc += Z[r * 8 + k] * Y[k * 8 + c];
        float g = ((r == c) ? 1.5f : 0.f) - 0.5f * acc;
        __syncthreads();
        G[t] = g;
        __syncthreads();
        float ny = 0.f, nz = 0.f;
#pragma unroll
        for (int k = 0; k < 8; k++) {
            ny += Y[r * 8 + k] * G[k * 8 + c];
            nz += G[r * 8 + k] * Z[k * 8 + c];
        }
        __syncthreads();
        Y[t] = ny;
        Z[t] = nz;
        __syncthreads();
    }

    g_dis[v * 64 + t] = Z[t] * rsqrtf(s);
}

// ---- one 64-thread block per nonzero 8x8 output block, filtered to node
//      band [c0, c1) so it can pipeline behind the band memsets ----
__global__ void k_blocks(const float* __restrict__ R, const int* __restrict__ E,
                         const float* __restrict__ L1, float* __restrict__ out,
                         int P, int n, int c0, int c1) {
    __shared__ float M1[64], M2[64], Di[64], Dj[64], B[64], T[64];
    int b = blockIdx.x;
    int t = threadIdx.x;          // 0..63
    bool is_edge = (b < P);
    int i, j;
    if (is_edge) {
        int2 e = ((const int2*)E)[b];
        i = e.x; j = e.y;
    } else {
        i = j = b - P;
    }
    if (i < c0 || i >= c1) return;   // not this band

    int r = t >> 3, c = t & 7;
    int g = t & 15, sel = t >> 4;     // cooperative float4 loads
    float sgn = 0.f;

    if (is_edge) {
        int rev = g_lookup[j * n + i];
        float l = L1[(size_t)i * n + j];
        sgn = (l > 0.f) ? 1.f : ((l < 0.f) ? -1.f : 0.f);
        if (sel == 0) {
            float4 v = make_float4(0.f, 0.f, 0.f, 0.f);
            if (rev >= 0) v = ((const float4*)(R + (size_t)rev * 64))[g];
            ((float4*)M1)[g] = v;                                   // R_ji
        } else if (sel == 1) {
            ((float4*)M2)[g] = ((const float4*)(R + (size_t)b * 64))[g];  // R_ij
        } else if (sel == 2) {
            ((float4*)Di)[g] = ((const float4*)(g_dis + (size_t)i * 64))[g];
        } else {
            ((float4*)Dj)[g] = ((const float4*)(g_dis + (size_t)j * 64))[g];
        }
    } else {
        if (sel == 0) {
            ((float4*)B)[g]  = ((const float4*)(g_diag + (size_t)i * 64))[g];
        } else if (sel == 2) {
            ((float4*)Di)[g] = ((const float4*)(g_dis + (size_t)i * 64))[g];
        } else if (sel == 3) {
            ((float4*)Dj)[g] = ((const float4*)(g_dis + (size_t)i * 64))[g];
        }
    }
    __syncthreads();

    if (is_edge) {
        float s = 0.f;
#pragma unroll
        for (int k = 0; k < 8; k++) s += M1[k * 8 + r] * M2[k * 8 + c];
        B[t] = -sgn * s;
    }
    __syncthreads();
    {
        float s = 0.f;
#pragma unroll
        for (int k = 0; k < 8; k++) s += Di[r * 8 + k] * B[k * 8 + c];
        T[t] = s;
    }
    __syncthreads();
    {
        float s = 0.f;
#pragma unroll
        for (int k = 0; k < 8; k++) s += T[r * 8 + k] * Dj[k * 8 + c];
        size_t nd = (size_t)n * 8;
        out[((size_t)i * 8 + r) * nd + (size_t)j * 8 + c] = s;
    }
}

extern "C" void kernel_launch(void* const* d_in, const int* in_sizes, int n_in,
                              void* d_out, int out_size) {
    const float* R  = (const float*)d_in[0];  // (P, 8, 8)
    const int*   E  = (const int*)  d_in[1];  // (P, 2)
    const float* L1 = (const float*)d_in[3];  // (n, n)

    int P = in_sizes[1] / 2;
    int n = (int)(sqrt((double)in_sizes[3]) + 0.5);

    // one-time host-side resources (streams/events are NOT device memory)
    static bool inited = false;
    static cudaStream_t side;
    static cudaEvent_t ev_fork, ev_pre, ev_join;
    static cudaEvent_t ev_band[CHUNKS];
    static void* lut_ptr;
    static void* diag_ptr;
    if (!inited) {
        cudaStreamCreateWithFlags(&side, cudaStreamNonBlocking);
        cudaEventCreateWithFlags(&ev_fork, cudaEventDisableTiming);
        cudaEventCreateWithFlags(&ev_pre, cudaEventDisableTiming);
        cudaEventCreateWithFlags(&ev_join, cudaEventDisableTiming);
        for (int c = 0; c < CHUNKS; c++)
            cudaEventCreateWithFlags(&ev_band[c], cudaEventDisableTiming);
        cudaGetSymbolAddress(&lut_ptr, g_lookup);
        cudaGetSymbolAddress(&diag_ptr, g_diag);
        inited = true;
    }

    int rpc = (n + CHUNKS - 1) / CHUNKS;              // node rows per band
    size_t total_bytes = (size_t)out_size * sizeof(float);
    size_t band_bytes = (size_t)rpc * 8 * (size_t)n * 8 * sizeof(float);

    // fork side stream at t=0; it zeroes the whole output in CHUNKS bands
    cudaEventRecord(ev_fork, 0);
    cudaStreamWaitEvent(side, ev_fork, 0);
    for (int c = 0; c < CHUNKS; c++) {
        size_t off = (size_t)c * band_bytes;
        size_t len = 0;
        if (off < total_bytes) {
            len = band_bytes;
            if (off + len > total_bytes) len = total_bytes - off;
            cudaMemsetAsync((char*)d_out + off, 0, len, side);
        }
        cudaEventRecord(ev_band[c], side);
    }

    // main stream: prefix chain (hidden under the memsets)
    cudaMemsetAsync(lut_ptr, 0xFF, (size_t)n * n * sizeof(int), 0);   // -1 fill
    cudaMemsetAsync(diag_ptr, 0, (size_t)n * 64 * sizeof(float), 0);
    k_lookup<<<(P + 255) / 256, 256>>>(E, P, n);
    k_ftf<<<(P * 64 + 255) / 256, 256>>>(R, E, P, n);
    k_ns<<<n, 64>>>(n);
    cudaEventRecord(ev_pre, 0);
    cudaStreamWaitEvent(side, ev_pre, 0);   // side-stream k_blocks also need prefix

    // pipelined block writer: band c waits on its memset; alternate streams
    for (int c = 0; c < CHUNKS; c++) {
        int c0 = c * rpc;
        if (c0 >= n) break;
        int c1 = (c0 + rpc < n) ? (c0 + rpc) : n;
        cudaStream_t s = (c & 1) ? side : (cudaStream_t)0;
        cudaStreamWaitEvent(s, ev_band[c], 0);
        k_blocks<<<P + n, 64, 0, s>>>(R, E, L1, (float*)d_out, P, n, c0, c1);
    }

    // join: side stream's writes must be ordered before launch completion
    cudaEventRecord(ev_join, side);
    cudaStreamWaitEvent(0, ev_join, 0);
}